// round 8
// baseline (speedup 1.0000x reference)
#include <cuda_runtime.h>
#include <stdint.h>

// Problem constants (fixed by the reference setup)
#define Bn 16
#define Pn 784
#define Dn 10000
#define Ln 1000
#define Cn 10

#define WSTRIDE 320   // padded words per row (320*32 = 10240 >= 10000)
#define NSLAB   10    // 10 slabs of 32 words each
#define NCTA    (Bn * NSLAB)  // 160 CTAs

// Dynamic smem layout (words): sVb[32000] | sIdx[784] | buf[16*10*33] | enc[32]
#define SM_VB   0
#define SM_IDX  32000
#define SM_BUF  (32000 + 784)
#define SM_ENC  (SM_BUF + 16 * 10 * 33)
#define SM_WORDS (SM_ENC + 32)
#define SMEM_BYTES (SM_WORDS * 4)

// Scratch (allocation-free: device globals)
__device__ uint32_t g_vbits[Ln * WSTRIDE];   // sign bits of value_weight
__device__ uint32_t g_pbits[Pn * WSTRIDE];   // sign bits of position_weight
__device__ int      g_idx[Bn * Pn];          // level index per (b, pixel)
__device__ float    g_partial[NSLAB * Bn * Cn];
__device__ int      g_ctr;                   // last-CTA counter (reset each run)

// ---------------------------------------------------------------------------
// Kernel 1: compute idx, pack sign bits of both bipolar tables.
// Permuted bit layout: word w, bit l  <->  dim d = (w>>2)*128 + l*4 + (w&3).
// Warp-task = 512 dims: 4 lane-contiguous float4 loads (fully coalesced),
// sign extraction via FSETP feeding VOTE directly, 16 ballots -> 16 words.
// ---------------------------------------------------------------------------
__global__ void __launch_bounds__(256) pack_kernel(const float* __restrict__ x,
                                                   const float* __restrict__ posw,
                                                   const float* __restrict__ valw)
{
    const int tid     = blockIdx.x * blockDim.x + threadIdx.x;
    const int nthread = gridDim.x * blockDim.x;

    if (tid == 0) g_ctr = 0;   // reset fused-finalize counter for this replay

    // level index: idx = clamp(rint(x*999), 0, 999)  (rintf = half-to-even)
    for (int i = tid; i < Bn * Pn; i += nthread) {
        int q = (int)rintf(x[i] * 999.0f);
        g_idx[i] = min(max(q, 0), Ln - 1);
    }

    const int lane   = threadIdx.x & 31;
    const int warpId = tid >> 5;
    const int nWarps = nthread >> 5;
    const int totalTasks = (Ln + Pn) * 20;   // 20 x 512-dim tasks per row

    for (int task = warpId; task < totalTasks; task += nWarps) {
        int row = task / 20;
        int s   = task - row * 20;
        const float* src;
        uint32_t* dst;
        if (row < Ln) {
            src = valw + (size_t)row * Dn;
            dst = g_vbits + row * WSTRIDE;
        } else {
            src = posw + (size_t)(row - Ln) * Dn;
            dst = g_pbits + (row - Ln) * WSTRIDE;
        }

        uint32_t myword = 0;
        if (s < 19) {
            float4 v0 = *reinterpret_cast<const float4*>(src + s * 512 +   0 + lane * 4);
            float4 v1 = *reinterpret_cast<const float4*>(src + s * 512 + 128 + lane * 4);
            float4 v2 = *reinterpret_cast<const float4*>(src + s * 512 + 256 + lane * 4);
            float4 v3 = *reinterpret_cast<const float4*>(src + s * 512 + 384 + lane * 4);
#define PK(sub, vv)                                                          \
            {                                                                \
                uint32_t b0 = __ballot_sync(0xffffffffu, (vv).x < 0.0f);     \
                uint32_t b1 = __ballot_sync(0xffffffffu, (vv).y < 0.0f);     \
                uint32_t b2 = __ballot_sync(0xffffffffu, (vv).z < 0.0f);     \
                uint32_t b3 = __ballot_sync(0xffffffffu, (vv).w < 0.0f);     \
                if (lane == (sub)*4 + 0) myword = b0;                        \
                if (lane == (sub)*4 + 1) myword = b1;                        \
                if (lane == (sub)*4 + 2) myword = b2;                        \
                if (lane == (sub)*4 + 3) myword = b3;                        \
            }
            PK(0, v0) PK(1, v1) PK(2, v2) PK(3, v3)
#undef PK
        } else {
            // tail task (dims 9728..10239): per-lane validity
#pragma unroll
            for (int sub = 0; sub < 4; sub++) {
                int d0 = s * 512 + sub * 128 + lane * 4;
                bool valid = d0 < Dn;            // Dn % 4 == 0
                float4 v = make_float4(0.f, 0.f, 0.f, 0.f);
                if (valid) v = *reinterpret_cast<const float4*>(src + d0);
                uint32_t b0 = __ballot_sync(0xffffffffu, valid && v.x < 0.0f);
                uint32_t b1 = __ballot_sync(0xffffffffu, valid && v.y < 0.0f);
                uint32_t b2 = __ballot_sync(0xffffffffu, valid && v.z < 0.0f);
                uint32_t b3 = __ballot_sync(0xffffffffu, valid && v.w < 0.0f);
                if (lane == sub * 4 + 0) myword = b0;
                if (lane == sub * 4 + 1) myword = b1;
                if (lane == sub * 4 + 2) myword = b2;
                if (lane == sub * 4 + 3) myword = b3;
            }
        }
        if (lane < 16) dst[s * 16 + lane] = myword;      // coalesced 64B
    }
}

// ---------------------------------------------------------------------------
__device__ __forceinline__ void fadd(uint32_t a, uint32_t b, uint32_t cin,
                                     uint32_t& s, uint32_t& cout)
{
    uint32_t t = a ^ b;
    s    = t ^ cin;
    cout = (a & b) | (cin & t);
}

// ---------------------------------------------------------------------------
// Kernel 2: CTA = (batch, slab), 1024 threads = 32 warps x 24-25 pixels.
// The slab's vbits columns (1000 levels x 32 words = 128KB) are staged in
// smem, converting the random gather to 29-cycle LDS. pbits stream from L2
// with one-group prefetch. 5-round tree reduction; threshold; coalesced
// classify; fused last-CTA finalize. Deterministic throughout.
// ---------------------------------------------------------------------------
__global__ void __launch_bounds__(1024) hdc_main_kernel(const float* __restrict__ cw,
                                                        float* __restrict__ out)
{
    const int b    = blockIdx.x / NSLAB;
    const int slab = blockIdx.x - b * NSLAB;
    const int tid  = threadIdx.x;
    const int lane = tid & 31;
    const int wsub = tid >> 5;                   // 0..31

    extern __shared__ uint32_t smem[];
    uint32_t* __restrict__ sVb  = smem + SM_VB;   // [1000][32]
    int*      __restrict__ sIdx = (int*)(smem + SM_IDX);
    uint32_t* __restrict__ sBuf = smem + SM_BUF;  // [16][10][33]
    uint32_t* __restrict__ sEnc = smem + SM_ENC;  // [32]
    __shared__ int sLast;

    // ---- load indices + stage vbits slab columns into smem ----
    if (tid < Pn) sIdx[tid] = g_idx[b * Pn + tid];

    const uint32_t* __restrict__ vsrc = g_vbits + slab * 32;
#pragma unroll
    for (int j = 0; j < 8; j++) {
        int i = tid + j * 1024;                  // i < 8000 uint4s
        if (j < 7 || i < 8000) {
            int row = i >> 3, q = i & 7;
            uint4 v = *reinterpret_cast<const uint4*>(vsrc + row * WSTRIDE + q * 4);
            *reinterpret_cast<uint4*>(sVb + row * 32 + q * 4) = v;
        }
    }
    __syncthreads();

    // ---- mainloop: warp wsub covers pixels [pstart, pstart+n) ----
    const int n      = (wsub < 16) ? 25 : 24;
    const int pstart = wsub * 24 + min(wsub, 16);
    const uint32_t* __restrict__ pbbase = g_pbits + slab * 32 + lane;

    uint32_t a[10];
#pragma unroll
    for (int j = 0; j < 10; j++) a[j] = 0u;

    // prefetch group 0 (7 pixels)
    uint32_t q[7]; int lvl[7];
#pragma unroll
    for (int k = 0; k < 7; k++) {
        int p = pstart + k;
        q[k]   = __ldg(pbbase + p * WSTRIDE);
        lvl[k] = sIdx[p];
    }

#pragma unroll
    for (int g = 0; g < 4; g++) {
        const int gn = (g < 3) ? 7 : (n - 21);   // 7,7,7,{3|4}
        uint32_t qn[7]; int lvln[7];
        if (g < 3) {                             // prefetch next group
            const int base = pstart + (g + 1) * 7;
            const int gnn  = (g < 2) ? 7 : (n - 21);
#pragma unroll
            for (int k = 0; k < 7; k++) {
                if (k < gnn) {
                    qn[k]   = __ldg(pbbase + (base + k) * WSTRIDE);
                    lvln[k] = sIdx[base + k];
                } else { qn[k] = 0u; lvln[k] = 0; }
            }
        }
        uint32_t t[7];
#pragma unroll
        for (int k = 0; k < 7; k++)
            t[k] = (k < gn) ? (sVb[lvl[k] * 32 + lane] ^ q[k]) : 0u;

        // 7:3 compressor -> (s3, s4, c4) with weights 1,2,4
        uint32_t s1, c1, s2, c2, s3, c3, s4, c4;
        fadd(t[0], t[1], t[2], s1, c1);
        fadd(t[3], t[4], t[5], s2, c2);
        fadd(s1,  s2,  t[6],  s3, c3);
        fadd(c1,  c2,  c3,    s4, c4);
        // merge 3-bit value into 5-plane counter (max 25 < 32)
        uint32_t carry = a[0] & s3; a[0] ^= s3;
        uint32_t s, co;
        fadd(a[1], s4, carry, s, co); a[1] = s; carry = co;
        fadd(a[2], c4, carry, s, co); a[2] = s; carry = co;
        { uint32_t nc = a[3] ^ carry; carry &= a[3]; a[3] = nc; }
        a[4] ^= carry;
#pragma unroll
        for (int k = 0; k < 7; k++) { q[k] = qn[k]; lvl[k] = lvln[k]; }
    }

    // ---- 5-round tree reduction across 32 warps ----
#pragma unroll
    for (int r = 0; r < 5; r++) {
        const int half = 16 >> r;                // 16,8,4,2,1 readers
        const int np   = 5 + r;                  // planes valid in sources
        if (wsub >= half && wsub < 2 * half) {
#pragma unroll
            for (int j = 0; j < 10; j++)
                if (j < np) sBuf[((wsub - half) * 10 + j) * 33 + lane] = a[j];
        }
        __syncthreads();
        if (wsub < half) {
            uint32_t carry = 0u;
#pragma unroll
            for (int j = 0; j < 10; j++) {
                if (j < np) {
                    uint32_t s, co;
                    fadd(a[j], sBuf[(wsub * 10 + j) * 33 + lane], carry, s, co);
                    a[j] = s; carry = co;
                } else if (j == np) {
                    a[j] = carry;                // planes >= np were zero
                }
            }
        }
        __syncthreads();
    }

    if (wsub == 0) {
        // enc = +1 iff count < 392 (392 = 0b110001000)
        uint32_t eq = ~0u, lt = 0u;
        eq &= ~a[9];
        lt |= eq & ~a[8]; eq &= a[8];
        lt |= eq & ~a[7]; eq &= a[7];
        eq &= ~a[6]; eq &= ~a[5]; eq &= ~a[4];
        lt |= eq & ~a[3];
        sEnc[lane] = lt;                         // bit set -> enc = +1
    }
    __syncthreads();

    // ---- coalesced classify: warp wsub (<10) handles class wsub.
    // float4 at dims [d0, d0+3] (d0 = slab*1024 + i*128 + lane*4) maps to
    // bit lane of words i*4+{0..3}; get words via shfl.
    if (wsub < Cn) {
        const uint32_t encReg = sEnc[lane];
        const float* __restrict__ wrow = cw + wsub * Dn + slab * 1024;
        float acc = 0.0f;
#pragma unroll
        for (int i = 0; i < 8; i++) {
            uint32_t w0 = __shfl_sync(0xffffffffu, encReg, i * 4 + 0);
            uint32_t w1 = __shfl_sync(0xffffffffu, encReg, i * 4 + 1);
            uint32_t w2 = __shfl_sync(0xffffffffu, encReg, i * 4 + 2);
            uint32_t w3 = __shfl_sync(0xffffffffu, encReg, i * 4 + 3);
            int d0 = slab * 1024 + i * 128 + lane * 4;
            if (d0 < Dn) {                       // Dn%4==0 -> whole float4 valid
                float4 v = *reinterpret_cast<const float4*>(wrow + i * 128 + lane * 4);
                acc += ((w0 >> lane) & 1u) ? v.x : -v.x;
                acc += ((w1 >> lane) & 1u) ? v.y : -v.y;
                acc += ((w2 >> lane) & 1u) ? v.z : -v.z;
                acc += ((w3 >> lane) & 1u) ? v.w : -v.w;
            }
        }
        // deterministic fixed-order warp reduction
#pragma unroll
        for (int off = 16; off >= 1; off >>= 1)
            acc += __shfl_xor_sync(0xffffffffu, acc, off);
        if (lane == 0) g_partial[(slab * Bn + b) * Cn + wsub] = acc;
    }

    // ---- fused finalize: last CTA reduces g_partial and writes out ----
    __syncthreads();
    if (tid == 0) {
        __threadfence();                         // publish g_partial writes
        int prev = atomicAdd(&g_ctr, 1);
        sLast = (prev == NCTA - 1);
    }
    __syncthreads();
    if (sLast) {
        __threadfence();                         // acquire all g_partial
        if (tid < Bn * Cn) {
            float s = 0.0f;
#pragma unroll
            for (int sl = 0; sl < NSLAB; sl++) s += g_partial[sl * Bn * Cn + tid];
            out[tid] = s;
        }
        if (tid == 0) g_ctr = 0;                 // reset for next replay
    }
}

// ---------------------------------------------------------------------------
extern "C" void kernel_launch(void* const* d_in, const int* in_sizes, int n_in,
                              void* d_out, int out_size)
{
    const float* x    = (const float*)d_in[0];   // [16,28,28]
    const float* posw = (const float*)d_in[1];   // [784,10000]
    const float* valw = (const float*)d_in[2];   // [1000,10000]
    const float* cw   = (const float*)d_in[3];   // [10,10000]
    float* out = (float*)d_out;                  // [16,10]

    cudaFuncSetAttribute(hdc_main_kernel,
                         cudaFuncAttributeMaxDynamicSharedMemorySize, SMEM_BYTES);

    pack_kernel<<<1184, 256>>>(x, posw, valw);
    hdc_main_kernel<<<NCTA, 1024, SMEM_BYTES>>>(cw, out);
}

// round 9
// speedup vs baseline: 1.0849x; 1.0849x over previous
#include <cuda_runtime.h>
#include <stdint.h>

// Problem constants (fixed by the reference setup)
#define Bn 16
#define Pn 784
#define Dn 10000
#define Ln 1000
#define Cn 10

#define WSTRIDE 320    // padded words per row (320*32 = 10240 >= 10000)
#define NSLAB   10     // 10 slabs of 32 words each
#define NQUAD   4      // pixel quads of 196
#define NGROUP  (Bn * NSLAB)          // 160 (b, slab) groups
#define NCTA    (NGROUP * NQUAD)      // 640 phase-A CTAs

// Scratch (allocation-free: device globals)
__device__ uint32_t g_vbits[Ln * WSTRIDE];     // sign bits of value_weight
__device__ uint32_t g_pbits[Pn * WSTRIDE];     // sign bits of position_weight
__device__ int      g_idx[Bn * Pn];            // level index per (b, pixel)
__device__ uint32_t g_quad[NGROUP * NQUAD * 8 * 32];  // 8-plane partial counts
__device__ float    g_partial[NSLAB * Bn * Cn];
__device__ int      g_gctr[NGROUP];            // per-group arrival counters
__device__ int      g_ctr2;                    // phase-B completion counter

// ---------------------------------------------------------------------------
// Kernel 1: compute idx, pack sign bits of both bipolar tables.
// Permuted bit layout: word w, bit l  <->  dim d = (w>>2)*128 + l*4 + (w&3).
// Warp-task = 512 dims: 4 lane-contiguous float4 loads (fully coalesced),
// sign extraction via FSETP feeding VOTE directly, 16 ballots -> 16 words.
// ---------------------------------------------------------------------------
__global__ void __launch_bounds__(256) pack_kernel(const float* __restrict__ x,
                                                   const float* __restrict__ posw,
                                                   const float* __restrict__ valw)
{
    const int tid     = blockIdx.x * blockDim.x + threadIdx.x;
    const int nthread = gridDim.x * blockDim.x;

    // level index: idx = clamp(rint(x*999), 0, 999)  (rintf = half-to-even)
    for (int i = tid; i < Bn * Pn; i += nthread) {
        int q = (int)rintf(x[i] * 999.0f);
        g_idx[i] = min(max(q, 0), Ln - 1);
    }

    const int lane   = threadIdx.x & 31;
    const int warpId = tid >> 5;
    const int nWarps = nthread >> 5;
    const int totalTasks = (Ln + Pn) * 20;   // 20 x 512-dim tasks per row

    for (int task = warpId; task < totalTasks; task += nWarps) {
        int row = task / 20;
        int s   = task - row * 20;
        const float* src;
        uint32_t* dst;
        if (row < Ln) {
            src = valw + (size_t)row * Dn;
            dst = g_vbits + row * WSTRIDE;
        } else {
            src = posw + (size_t)(row - Ln) * Dn;
            dst = g_pbits + (row - Ln) * WSTRIDE;
        }

        uint32_t myword = 0;
        if (s < 19) {
            float4 v0 = *reinterpret_cast<const float4*>(src + s * 512 +   0 + lane * 4);
            float4 v1 = *reinterpret_cast<const float4*>(src + s * 512 + 128 + lane * 4);
            float4 v2 = *reinterpret_cast<const float4*>(src + s * 512 + 256 + lane * 4);
            float4 v3 = *reinterpret_cast<const float4*>(src + s * 512 + 384 + lane * 4);
#define PK(sub, vv)                                                          \
            {                                                                \
                uint32_t b0 = __ballot_sync(0xffffffffu, (vv).x < 0.0f);     \
                uint32_t b1 = __ballot_sync(0xffffffffu, (vv).y < 0.0f);     \
                uint32_t b2 = __ballot_sync(0xffffffffu, (vv).z < 0.0f);     \
                uint32_t b3 = __ballot_sync(0xffffffffu, (vv).w < 0.0f);     \
                if (lane == (sub)*4 + 0) myword = b0;                        \
                if (lane == (sub)*4 + 1) myword = b1;                        \
                if (lane == (sub)*4 + 2) myword = b2;                        \
                if (lane == (sub)*4 + 3) myword = b3;                        \
            }
            PK(0, v0) PK(1, v1) PK(2, v2) PK(3, v3)
#undef PK
        } else {
            // tail task (dims 9728..10239): per-lane validity
#pragma unroll
            for (int sub = 0; sub < 4; sub++) {
                int d0 = s * 512 + sub * 128 + lane * 4;
                bool valid = d0 < Dn;            // Dn % 4 == 0
                float4 v = make_float4(0.f, 0.f, 0.f, 0.f);
                if (valid) v = *reinterpret_cast<const float4*>(src + d0);
                uint32_t b0 = __ballot_sync(0xffffffffu, valid && v.x < 0.0f);
                uint32_t b1 = __ballot_sync(0xffffffffu, valid && v.y < 0.0f);
                uint32_t b2 = __ballot_sync(0xffffffffu, valid && v.z < 0.0f);
                uint32_t b3 = __ballot_sync(0xffffffffu, valid && v.w < 0.0f);
                if (lane == sub * 4 + 0) myword = b0;
                if (lane == sub * 4 + 1) myword = b1;
                if (lane == sub * 4 + 2) myword = b2;
                if (lane == sub * 4 + 3) myword = b3;
            }
        }
        if (lane < 16) dst[s * 16 + lane] = myword;      // coalesced 64B
    }
}

// ---------------------------------------------------------------------------
__device__ __forceinline__ void fadd(uint32_t a, uint32_t b, uint32_t cin,
                                     uint32_t& s, uint32_t& cout)
{
    uint32_t t = a ^ b;
    s    = t ^ cin;
    cout = (a & b) | (cin & t);
}

// ---------------------------------------------------------------------------
// Kernel 2: CTA = (batch, slab, quad), 256 threads = 8 warps x 24-25 pixels.
// 640 CTAs -> ~4-5 CTAs/SM resident: gather latency hidden by TLP.
// Phase A: CSA count of 196 pixels -> 8-plane partial to global.
// Phase B (4th CTA of each group): sum 4 quads -> threshold -> enc ->
// coalesced classify. 160th phase-B completion writes final output.
// Deterministic: fixed-order reductions, int atomics only.
// ---------------------------------------------------------------------------
__global__ void __launch_bounds__(256) hdc_main_kernel(const float* __restrict__ cw,
                                                       float* __restrict__ out)
{
    const int b    = blockIdx.x / (NSLAB * NQUAD);
    const int r0   = blockIdx.x - b * (NSLAB * NQUAD);
    const int slab = r0 / NQUAD;
    const int quad = r0 - slab * NQUAD;
    const int grp  = b * NSLAB + slab;
    const int tid  = threadIdx.x;
    const int lane = tid & 31;
    const int wsub = tid >> 5;                   // 0..7

    __shared__ int      sIdx[196];
    __shared__ uint32_t sBuf[4][8][33];
    __shared__ uint32_t sEnc[32];
    __shared__ int      sDoB, sLast;

    if (tid < 196) sIdx[tid] = g_idx[b * Pn + quad * 196 + tid];
    __syncthreads();

    // ---- phase A: count this quad's 196 pixels ----
    const int base = wsub * 24 + min(wsub, 4);   // local pixel offset
    const int n    = (wsub < 4) ? 25 : 24;
    const uint32_t* __restrict__ vb = g_vbits + slab * 32 + lane;
    const uint32_t* __restrict__ pb = g_pbits + (quad * 196 + base) * WSTRIDE
                                              + slab * 32 + lane;

    uint32_t a[8];
#pragma unroll
    for (int j = 0; j < 8; j++) a[j] = 0u;

#pragma unroll
    for (int g = 0; g < 4; g++) {
        const int gn = (g < 3) ? 7 : (n - 21);   // 7,7,7,{3|4}
        uint32_t t[7];
#pragma unroll
        for (int k = 0; k < 7; k++) {
            if (k < gn) {
                int lvl = sIdx[base + g * 7 + k];
                t[k] = __ldg(vb + lvl * WSTRIDE) ^ __ldg(pb + (g * 7 + k) * WSTRIDE);
            } else t[k] = 0u;
        }
        // 7:3 compressor -> (s3, s4, c4) with weights 1,2,4
        uint32_t s1, c1, s2, c2, s3, c3, s4, c4;
        fadd(t[0], t[1], t[2], s1, c1);
        fadd(t[3], t[4], t[5], s2, c2);
        fadd(s1,  s2,  t[6],  s3, c3);
        fadd(c1,  c2,  c3,    s4, c4);
        // merge 3-bit value into 5-plane counter (max 25 < 32)
        uint32_t carry = a[0] & s3; a[0] ^= s3;
        uint32_t s, co;
        fadd(a[1], s4, carry, s, co); a[1] = s; carry = co;
        fadd(a[2], c4, carry, s, co); a[2] = s; carry = co;
        { uint32_t nc = a[3] ^ carry; carry &= a[3]; a[3] = nc; }
        a[4] ^= carry;
    }

    // ---- 3-round tree reduction across 8 warps (5 -> 8 planes) ----
#pragma unroll
    for (int r = 0; r < 3; r++) {
        const int half = 4 >> r;                 // 4,2,1 readers
        const int np   = 5 + r;                  // planes valid in sources
        if (wsub >= half && wsub < 2 * half) {
#pragma unroll
            for (int j = 0; j < 8; j++)
                if (j < np) sBuf[wsub - half][j][lane] = a[j];
        }
        __syncthreads();
        if (wsub < half) {
            uint32_t carry = 0u;
#pragma unroll
            for (int j = 0; j < 8; j++) {
                if (j < np) {
                    uint32_t s, co;
                    fadd(a[j], sBuf[wsub][j][lane], carry, s, co);
                    a[j] = s; carry = co;
                } else if (j == np) {
                    a[j] = carry;
                }
            }
        }
        __syncthreads();
    }

    if (wsub == 0) {                             // write 8-plane partial
#pragma unroll
        for (int j = 0; j < 8; j++)
            g_quad[((grp * NQUAD + quad) * 8 + j) * 32 + lane] = a[j];
    }
    __syncthreads();

    // ---- group arrival: 4th CTA of this (b,slab) runs phase B ----
    if (tid == 0) {
        __threadfence();
        int prev = atomicAdd(&g_gctr[grp], 1);
        sDoB = (prev == NQUAD - 1);
        if (sDoB) g_gctr[grp] = 0;               // reset for next replay
    }
    __syncthreads();
    if (!sDoB) return;

    __threadfence();                             // acquire peer quad counts

    // ---- phase B: sum 4 quads -> 10 planes -> enc ----
    if (wsub == 0) {
        uint32_t s[10];
#pragma unroll
        for (int j = 0; j < 8; j++)
            s[j] = g_quad[((grp * NQUAD + 0) * 8 + j) * 32 + lane];
        s[8] = s[9] = 0u;
#pragma unroll
        for (int q = 1; q < NQUAD; q++) {
            uint32_t carry = 0u;
#pragma unroll
            for (int j = 0; j < 8; j++) {
                uint32_t v = g_quad[((grp * NQUAD + q) * 8 + j) * 32 + lane];
                uint32_t ss, co;
                fadd(s[j], v, carry, ss, co);
                s[j] = ss; carry = co;
            }
            { uint32_t nc = s[8] ^ carry; carry &= s[8]; s[8] = nc; }
            s[9] ^= carry;
        }
        // enc = +1 iff count < 392 (392 = 0b0110001000)
        uint32_t eq = ~0u, lt = 0u;
        eq &= ~s[9];
        lt |= eq & ~s[8]; eq &= s[8];
        lt |= eq & ~s[7]; eq &= s[7];
        eq &= ~s[6]; eq &= ~s[5]; eq &= ~s[4];
        lt |= eq & ~s[3];
        sEnc[lane] = lt;                         // bit set -> enc = +1
    }
    __syncthreads();

    // ---- coalesced classify: warp wsub handles classes {wsub, wsub+8}.
    // float4 at dims [d0, d0+3] (d0 = slab*1024 + i*128 + lane*4) maps to
    // bit lane of words i*4+{0..3}; get words via shfl.
    const uint32_t encReg = sEnc[lane];
    for (int c = wsub; c < Cn; c += 8) {
        const float* __restrict__ wrow = cw + c * Dn + slab * 1024;
        float acc = 0.0f;
#pragma unroll
        for (int i = 0; i < 8; i++) {
            uint32_t w0 = __shfl_sync(0xffffffffu, encReg, i * 4 + 0);
            uint32_t w1 = __shfl_sync(0xffffffffu, encReg, i * 4 + 1);
            uint32_t w2 = __shfl_sync(0xffffffffu, encReg, i * 4 + 2);
            uint32_t w3 = __shfl_sync(0xffffffffu, encReg, i * 4 + 3);
            int d0 = slab * 1024 + i * 128 + lane * 4;
            if (d0 < Dn) {                       // Dn%4==0 -> whole float4 valid
                float4 v = *reinterpret_cast<const float4*>(wrow + i * 128 + lane * 4);
                acc += ((w0 >> lane) & 1u) ? v.x : -v.x;
                acc += ((w1 >> lane) & 1u) ? v.y : -v.y;
                acc += ((w2 >> lane) & 1u) ? v.z : -v.z;
                acc += ((w3 >> lane) & 1u) ? v.w : -v.w;
            }
        }
        // deterministic fixed-order warp reduction
#pragma unroll
        for (int off = 16; off >= 1; off >>= 1)
            acc += __shfl_xor_sync(0xffffffffu, acc, off);
        if (lane == 0) g_partial[(slab * Bn + b) * Cn + c] = acc;
    }

    // ---- 160th phase-B completion writes the final output ----
    __syncthreads();
    if (tid == 0) {
        __threadfence();
        int prev = atomicAdd(&g_ctr2, 1);
        sLast = (prev == NGROUP - 1);
    }
    __syncthreads();
    if (sLast) {
        __threadfence();
        if (tid < Bn * Cn) {
            float s = 0.0f;
#pragma unroll
            for (int sl = 0; sl < NSLAB; sl++) s += g_partial[sl * Bn * Cn + tid];
            out[tid] = s;
        }
        if (tid == 0) g_ctr2 = 0;                // reset for next replay
    }
}

// ---------------------------------------------------------------------------
extern "C" void kernel_launch(void* const* d_in, const int* in_sizes, int n_in,
                              void* d_out, int out_size)
{
    const float* x    = (const float*)d_in[0];   // [16,28,28]
    const float* posw = (const float*)d_in[1];   // [784,10000]
    const float* valw = (const float*)d_in[2];   // [1000,10000]
    const float* cw   = (const float*)d_in[3];   // [10,10000]
    float* out = (float*)d_out;                  // [16,10]

    pack_kernel<<<1184, 256>>>(x, posw, valw);
    hdc_main_kernel<<<NCTA, 256>>>(cw, out);
}

// round 11
// speedup vs baseline: 1.1260x; 1.0379x over previous
#include <cuda_runtime.h>
#include <stdint.h>

// Problem constants (fixed by the reference setup)
#define Bn 16
#define Pn 784
#define Dn 10000
#define Ln 1000
#define Cn 10

#define WSTRIDE 320    // padded words per row (320*32 = 10240 >= 10000)
#define NSS     5      // 5 superslabs of 64 words
#define NCH     7      // 7 pixel chunks of 112 (8 warps x 14)
#define NBP     8      // 8 batch pairs
#define NGROUP  (NBP * NSS)          // 40 (bp, ss) groups
#define NCTA_A  (NGROUP * NCH)       // 280 phase-A CTAs

// Scratch (allocation-free: device globals)
__device__ uint32_t g_vbits[Ln * WSTRIDE];     // sign bits of value_weight
__device__ uint32_t g_pbits[Pn * WSTRIDE];     // sign bits of position_weight
__device__ uint32_t g_idx2[NBP * Pn];          // packed level idx pair (lo|hi<<16)
__device__ uint2    g_chunk[NCTA_A * 2 * 7 * 32]; // 7-plane chunk partials
__device__ float    g_partial[NSS * Bn * Cn];
__device__ int      g_gctr[NGROUP];            // per-group arrival counters
__device__ int      g_ctr2;                    // group completion counter

// ---------------------------------------------------------------------------
// Kernel 1: compute packed idx pairs, pack sign bits of both bipolar tables.
// Permuted bit layout: word w, bit l  <->  dim d = (w>>2)*128 + l*4 + (w&3).
// Warp-task = 512 dims: 4 lane-contiguous float4 loads (fully coalesced),
// sign extraction via FSETP feeding VOTE directly, 16 ballots -> 16 words.
// ---------------------------------------------------------------------------
__global__ void __launch_bounds__(256) pack_kernel(const float* __restrict__ x,
                                                   const float* __restrict__ posw,
                                                   const float* __restrict__ valw)
{
    const int tid     = blockIdx.x * blockDim.x + threadIdx.x;
    const int nthread = gridDim.x * blockDim.x;

    // packed level indices: idx = clamp(rint(x*999), 0, 999)  (half-to-even)
    for (int i = tid; i < NBP * Pn; i += nthread) {
        int bp = i / Pn, p = i - bp * Pn;
        int qa = (int)rintf(x[(2 * bp)     * Pn + p] * 999.0f);
        int qb = (int)rintf(x[(2 * bp + 1) * Pn + p] * 999.0f);
        qa = min(max(qa, 0), Ln - 1);
        qb = min(max(qb, 0), Ln - 1);
        g_idx2[i] = (uint32_t)qa | ((uint32_t)qb << 16);
    }

    const int lane   = threadIdx.x & 31;
    const int warpId = tid >> 5;
    const int nWarps = nthread >> 5;
    const int totalTasks = (Ln + Pn) * 20;   // 20 x 512-dim tasks per row

    for (int task = warpId; task < totalTasks; task += nWarps) {
        int row = task / 20;
        int s   = task - row * 20;
        const float* src;
        uint32_t* dst;
        if (row < Ln) {
            src = valw + (size_t)row * Dn;
            dst = g_vbits + row * WSTRIDE;
        } else {
            src = posw + (size_t)(row - Ln) * Dn;
            dst = g_pbits + (row - Ln) * WSTRIDE;
        }

        uint32_t myword = 0;
        if (s < 19) {
            float4 v0 = *reinterpret_cast<const float4*>(src + s * 512 +   0 + lane * 4);
            float4 v1 = *reinterpret_cast<const float4*>(src + s * 512 + 128 + lane * 4);
            float4 v2 = *reinterpret_cast<const float4*>(src + s * 512 + 256 + lane * 4);
            float4 v3 = *reinterpret_cast<const float4*>(src + s * 512 + 384 + lane * 4);
#define PK(sub, vv)                                                          \
            {                                                                \
                uint32_t b0 = __ballot_sync(0xffffffffu, (vv).x < 0.0f);     \
                uint32_t b1 = __ballot_sync(0xffffffffu, (vv).y < 0.0f);     \
                uint32_t b2 = __ballot_sync(0xffffffffu, (vv).z < 0.0f);     \
                uint32_t b3 = __ballot_sync(0xffffffffu, (vv).w < 0.0f);     \
                if (lane == (sub)*4 + 0) myword = b0;                        \
                if (lane == (sub)*4 + 1) myword = b1;                        \
                if (lane == (sub)*4 + 2) myword = b2;                        \
                if (lane == (sub)*4 + 3) myword = b3;                        \
            }
            PK(0, v0) PK(1, v1) PK(2, v2) PK(3, v3)
#undef PK
        } else {
            // tail task (dims 9728..10239): per-lane validity
#pragma unroll
            for (int sub = 0; sub < 4; sub++) {
                int d0 = s * 512 + sub * 128 + lane * 4;
                bool valid = d0 < Dn;            // Dn % 4 == 0
                float4 v = make_float4(0.f, 0.f, 0.f, 0.f);
                if (valid) v = *reinterpret_cast<const float4*>(src + d0);
                uint32_t b0 = __ballot_sync(0xffffffffu, valid && v.x < 0.0f);
                uint32_t b1 = __ballot_sync(0xffffffffu, valid && v.y < 0.0f);
                uint32_t b2 = __ballot_sync(0xffffffffu, valid && v.z < 0.0f);
                uint32_t b3 = __ballot_sync(0xffffffffu, valid && v.w < 0.0f);
                if (lane == sub * 4 + 0) myword = b0;
                if (lane == sub * 4 + 1) myword = b1;
                if (lane == sub * 4 + 2) myword = b2;
                if (lane == sub * 4 + 3) myword = b3;
            }
        }
        if (lane < 16) dst[s * 16 + lane] = myword;      // coalesced 64B
    }
}

// ---------------------------------------------------------------------------
__device__ __forceinline__ void fadd(uint32_t a, uint32_t b, uint32_t cin,
                                     uint32_t& s, uint32_t& cout)
{
    uint32_t t = a ^ b;
    s    = t ^ cin;
    cout = (a & b) | (cin & t);
}

// 7:3 compress t[0..6] and merge into 4-plane counter cp[0..3] (max 14)
__device__ __forceinline__ void csa7_merge4(const uint32_t* t, uint32_t* cp)
{
    uint32_t s1, c1, s2, c2, s3, c3, s4, c4;
    fadd(t[0], t[1], t[2], s1, c1);
    fadd(t[3], t[4], t[5], s2, c2);
    fadd(s1,  s2,  t[6],  s3, c3);
    fadd(c1,  c2,  c3,    s4, c4);
    uint32_t carry = cp[0] & s3; cp[0] ^= s3;
    uint32_t s, co;
    fadd(cp[1], s4, carry, s, co); cp[1] = s; carry = co;
    fadd(cp[2], c4, carry, s, co); cp[2] = s; carry = co;
    cp[3] ^= carry;
}

// enc bit = 1 iff count < 392 (392 = 0b0110001000), 10 bit-planes
__device__ __forceinline__ uint32_t thr392(const uint32_t* c)
{
    uint32_t eq = ~0u, lt = 0u;
    eq &= ~c[9];
    lt |= eq & ~c[8]; eq &= c[8];
    lt |= eq & ~c[7]; eq &= c[7];
    eq &= ~c[6]; eq &= ~c[5]; eq &= ~c[4];
    lt |= eq & ~c[3];
    return lt;
}

// ---------------------------------------------------------------------------
// Kernel 2: CTA = (batch-pair, superslab of 64 words, chunk of 112 pixels),
// 256 threads = 8 warps x 14 pixels. Lane holds a WORD PAIR (uint2, LDG.64);
// the pbits stream is loaded once per pixel and shared by both batches;
// packed idx pairs give both levels in one smem read. 4-plane CSA per
// stream -> 3-round tree (7 planes) -> chunk partial. 7th CTA of each
// (bp,ss) group sums chunks -> threshold -> enc -> coalesced classify.
// 40th group completion writes out. Deterministic; int atomics only.
// ---------------------------------------------------------------------------
__global__ void __launch_bounds__(256) hdc_main_kernel(const float* __restrict__ cw,
                                                       float* __restrict__ out)
{
    const int bp   = blockIdx.x / (NSS * NCH);
    const int r0   = blockIdx.x - bp * (NSS * NCH);
    const int ss   = r0 / NCH;
    const int ch   = r0 - ss * NCH;
    const int grp  = bp * NSS + ss;
    const int tid  = threadIdx.x;
    const int lane = tid & 31;
    const int wsub = tid >> 5;                   // 0..7

    __shared__ uint32_t sIdx2[112];
    __shared__ uint2    sBuf[4][2][7][32];       // [src][b][plane][lane]
    __shared__ uint32_t sEnc[2][64];
    __shared__ int      sDoB, sLast;

    if (tid < 112) sIdx2[tid] = g_idx2[bp * Pn + ch * 112 + tid];
    __syncthreads();

    const int wbase = ss * 64 + 2 * lane;        // first word of this lane's pair
    const int p0    = ch * 112 + wsub * 14;      // global first pixel of this warp

    // counters: [batch][comp][plane], counts <= 14
    uint32_t cnt[2][2][4];
#pragma unroll
    for (int b = 0; b < 2; b++)
#pragma unroll
        for (int c = 0; c < 2; c++)
#pragma unroll
            for (int j = 0; j < 4; j++) cnt[b][c][j] = 0u;

#pragma unroll
    for (int g = 0; g < 2; g++) {                // 2 groups of 7 pixels
        const int pg  = p0 + g * 7;
        const int lg  = (wsub * 14 + g * 7);     // local pixel in chunk
        uint32_t pr[7]; uint2 q[7], va[7], vb[7];
#pragma unroll
        for (int k = 0; k < 7; k++) pr[k] = sIdx2[lg + k];
#pragma unroll
        for (int k = 0; k < 7; k++)
            q[k] = __ldg(reinterpret_cast<const uint2*>(g_pbits + (pg + k) * WSTRIDE + wbase));
#pragma unroll
        for (int k = 0; k < 7; k++)
            va[k] = __ldg(reinterpret_cast<const uint2*>(g_vbits + (pr[k] & 0xffffu) * WSTRIDE + wbase));
#pragma unroll
        for (int k = 0; k < 7; k++)
            vb[k] = __ldg(reinterpret_cast<const uint2*>(g_vbits + (pr[k] >> 16) * WSTRIDE + wbase));

        uint32_t t[7];
#pragma unroll
        for (int k = 0; k < 7; k++) t[k] = va[k].x ^ q[k].x;
        csa7_merge4(t, cnt[0][0]);
#pragma unroll
        for (int k = 0; k < 7; k++) t[k] = va[k].y ^ q[k].y;
        csa7_merge4(t, cnt[0][1]);
#pragma unroll
        for (int k = 0; k < 7; k++) t[k] = vb[k].x ^ q[k].x;
        csa7_merge4(t, cnt[1][0]);
#pragma unroll
        for (int k = 0; k < 7; k++) t[k] = vb[k].y ^ q[k].y;
        csa7_merge4(t, cnt[1][1]);
    }

    // ---- 3-round tree reduction across 8 warps: 4 -> 7 planes ----
    uint32_t a[2][2][7];
#pragma unroll
    for (int b = 0; b < 2; b++)
#pragma unroll
        for (int c = 0; c < 2; c++) {
#pragma unroll
            for (int j = 0; j < 4; j++) a[b][c][j] = cnt[b][c][j];
            a[b][c][4] = a[b][c][5] = a[b][c][6] = 0u;
        }

#pragma unroll
    for (int r = 0; r < 3; r++) {
        const int half = 4 >> r;                 // 4,2,1 readers
        const int np   = 4 + r;                  // planes valid in sources
        if (wsub >= half && wsub < 2 * half) {
#pragma unroll
            for (int b = 0; b < 2; b++)
#pragma unroll
                for (int j = 0; j < 7; j++)
                    if (j < np)
                        sBuf[wsub - half][b][j][lane] = make_uint2(a[b][0][j], a[b][1][j]);
        }
        __syncthreads();
        if (wsub < half) {
#pragma unroll
            for (int b = 0; b < 2; b++) {
                uint32_t cx = 0u, cy = 0u;
#pragma unroll
                for (int j = 0; j < 7; j++) {
                    if (j < np) {
                        uint2 v = sBuf[wsub][b][j][lane];
                        uint32_t s, co;
                        fadd(a[b][0][j], v.x, cx, s, co); a[b][0][j] = s; cx = co;
                        fadd(a[b][1][j], v.y, cy, s, co); a[b][1][j] = s; cy = co;
                    } else if (j == np) {
                        a[b][0][j] = cx; a[b][1][j] = cy;
                    }
                }
            }
        }
        __syncthreads();
    }

    if (wsub == 0) {                             // write 7-plane chunk partial
#pragma unroll
        for (int b = 0; b < 2; b++)
#pragma unroll
            for (int j = 0; j < 7; j++)
                g_chunk[((blockIdx.x * 2 + b) * 7 + j) * 32 + lane] =
                    make_uint2(a[b][0][j], a[b][1][j]);
    }
    __syncthreads();

    // ---- group arrival: 7th CTA of this (bp,ss) runs phase B ----
    if (tid == 0) {
        __threadfence();
        int prev = atomicAdd(&g_gctr[grp], 1);
        sDoB = (prev == NCH - 1);
        if (sDoB) g_gctr[grp] = 0;               // reset for next replay
    }
    __syncthreads();
    if (!sDoB) return;

    __threadfence();                             // acquire peer chunk partials

    // ---- phase B: warps 0,1 (one per batch) sum 7 chunks -> enc ----
    if (wsub < 2) {
        uint32_t s[2][10];
#pragma unroll
        for (int c = 0; c < 2; c++)
#pragma unroll
            for (int j = 0; j < 10; j++) s[c][j] = 0u;
#pragma unroll
        for (int c2 = 0; c2 < NCH; c2++) {
            const int cta = (grp * NCH + c2);
            uint32_t cx = 0u, cy = 0u;
#pragma unroll
            for (int j = 0; j < 7; j++) {
                uint2 v = g_chunk[((cta * 2 + wsub) * 7 + j) * 32 + lane];
                uint32_t ss2, co;
                fadd(s[0][j], v.x, cx, ss2, co); s[0][j] = ss2; cx = co;
                fadd(s[1][j], v.y, cy, ss2, co); s[1][j] = ss2; cy = co;
            }
#pragma unroll
            for (int j = 7; j < 10; j++) {
                uint32_t nc = s[0][j] ^ cx; cx &= s[0][j]; s[0][j] = nc;
                nc = s[1][j] ^ cy; cy &= s[1][j]; s[1][j] = nc;
            }
        }
        sEnc[wsub][2 * lane]     = thr392(s[0]);
        sEnc[wsub][2 * lane + 1] = thr392(s[1]);
    }
    __syncthreads();

    // ---- coalesced classify: unit u = b*10+c over dims [ss*2048, +2048).
    // float4 at d0 = ss*2048 + i*128 + lane*4 maps to bit lane of local
    // words i*4+{0..3}; enc words broadcast from smem.
    for (int u = wsub; u < 2 * Cn; u += 8) {
        const int b = u / Cn, c = u - (u / Cn) * Cn;
        const float* __restrict__ wrow = cw + c * Dn + ss * 2048;
        float acc = 0.0f;
#pragma unroll
        for (int i = 0; i < 16; i++) {
            int d0 = ss * 2048 + i * 128 + lane * 4;
            if (d0 < Dn) {                       // Dn%4==0 -> whole float4 valid
                uint32_t w0 = sEnc[b][i * 4 + 0];
                uint32_t w1 = sEnc[b][i * 4 + 1];
                uint32_t w2 = sEnc[b][i * 4 + 2];
                uint32_t w3 = sEnc[b][i * 4 + 3];
                float4 v = *reinterpret_cast<const float4*>(wrow + i * 128 + lane * 4);
                acc += ((w0 >> lane) & 1u) ? v.x : -v.x;
                acc += ((w1 >> lane) & 1u) ? v.y : -v.y;
                acc += ((w2 >> lane) & 1u) ? v.z : -v.z;
                acc += ((w3 >> lane) & 1u) ? v.w : -v.w;
            }
        }
        // deterministic fixed-order warp reduction
#pragma unroll
        for (int off = 16; off >= 1; off >>= 1)
            acc += __shfl_xor_sync(0xffffffffu, acc, off);
        if (lane == 0) g_partial[(ss * Bn + (bp * 2 + b)) * Cn + c] = acc;
    }

    // ---- 40th group completion writes the final output ----
    __syncthreads();
    if (tid == 0) {
        __threadfence();
        int prev = atomicAdd(&g_ctr2, 1);
        sLast = (prev == NGROUP - 1);
    }
    __syncthreads();
    if (sLast) {
        __threadfence();
        if (tid < Bn * Cn) {
            float s = 0.0f;
#pragma unroll
            for (int sl = 0; sl < NSS; sl++) s += g_partial[sl * Bn * Cn + tid];
            out[tid] = s;
        }
        if (tid == 0) g_ctr2 = 0;                // reset for next replay
    }
}

// ---------------------------------------------------------------------------
extern "C" void kernel_launch(void* const* d_in, const int* in_sizes, int n_in,
                              void* d_out, int out_size)
{
    const float* x    = (const float*)d_in[0];   // [16,28,28]
    const float* posw = (const float*)d_in[1];   // [784,10000]
    const float* valw = (const float*)d_in[2];   // [1000,10000]
    const float* cw   = (const float*)d_in[3];   // [10,10000]
    float* out = (float*)d_out;                  // [16,10]

    pack_kernel<<<1184, 256>>>(x, posw, valw);
    hdc_main_kernel<<<NCTA_A, 256>>>(cw, out);
}